// round 15
// baseline (speedup 1.0000x reference)
#include <cuda_runtime.h>

// out[b, f, s] = x[b, 0, s] * w[f, s] + bias[f, s]
// B=128, F=256, S=4096. HBM-write-bound: 512 MiB out (~6.8 TB/s achieved).
//
// R15: occupancy sweep step 4 — 8 CTAs/SM = 64 warps = 100% occupancy.
// FT=2 (16-reg w/bias cache), BT=4 (16 KB smem; 8 x 16 = 128 KB/SM).
// Same winning structure: x staged in smem, zero in-loop global loads,
// filter-inner 16 KB-stride __stcs bursts.

#define S4     1024        // float4 per row (4096 floats)
#define NFILT  256
#define BATCH  128
#define FT     2           // filters per block (w/bias register-cached)
#define BT     4           // batches per block (x staged in smem)
#define CHUNK4 256         // float4 per s-chunk, one per thread

__global__ __launch_bounds__(256, 8) void dense_filter_expand_kernel(
    const float4* __restrict__ x,     // [B, S4]
    const float4* __restrict__ w,     // [F, S4]
    const float4* __restrict__ bias,  // [F, S4]
    float4* __restrict__ out)         // [B, F, S4]
{
    __shared__ float4 xs[BT * CHUNK4];         // 16 KB

    const int t  = threadIdx.x;                // 0..255
    const int sc = blockIdx.x;                 // 0..3    s-chunk
    const int fg = blockIdx.y;                 // 0..127  filter group
    const int bg = blockIdx.z;                 // 0..31   batch group
    const int s4 = sc * CHUNK4 + t;            // float4 index within a row
    const int b0 = bg * BT;
    const int f0 = fg * FT;

    // Preamble: stage x chunks for 4 batches into smem (independent LDGs).
#pragma unroll
    for (int i = 0; i < BT; i++)
        xs[i * CHUNK4 + t] = __ldg(&x[(size_t)(b0 + i) * S4 + s4]);

    // Register-cache w/bias chunks for the 2 filters (16 regs).
    float4 wv[FT], bv[FT];
#pragma unroll
    for (int ff = 0; ff < FT; ff++) {
        wv[ff] = __ldg(&w[(size_t)(f0 + ff) * S4 + s4]);
        bv[ff] = __ldg(&bias[(size_t)(f0 + ff) * S4 + s4]);
    }
    __syncthreads();

    // Steady state: 1 LDS + 2 streaming stores per batch. Zero global loads.
#pragma unroll 1
    for (int bb = 0; bb < BT; bb++) {
        const float4 xv = xs[bb * CHUNK4 + t];

        float4* obase = out + ((size_t)(b0 + bb) * NFILT + f0) * S4 + s4;
#pragma unroll
        for (int ff = 0; ff < FT; ff++) {
            float4 o;
            o.x = fmaf(xv.x, wv[ff].x, bv[ff].x);
            o.y = fmaf(xv.y, wv[ff].y, bv[ff].y);
            o.z = fmaf(xv.z, wv[ff].z, bv[ff].z);
            o.w = fmaf(xv.w, wv[ff].w, bv[ff].w);
            // Streaming store: output is write-once, never re-read.
            __stcs(obase + (size_t)ff * S4, o);
        }
    }
}

extern "C" void kernel_launch(void* const* d_in, const int* in_sizes, int n_in,
                              void* d_out, int out_size) {
    const float4* x    = (const float4*)d_in[0];   // inputs [128,1,4096]
    const float4* w    = (const float4*)d_in[1];   // w [256,4096]
    const float4* bias = (const float4*)d_in[2];   // b [256,4096]
    float4* out = (float4*)d_out;

    dim3 grid(S4 / CHUNK4, NFILT / FT, BATCH / BT);  // (4, 128, 32) = 16384
    dense_filter_expand_kernel<<<grid, 256>>>(x, w, bias, out);
}

// round 16
// speedup vs baseline: 1.0278x; 1.0278x over previous
#include <cuda_runtime.h>

// out[b, f, s] = x[b, 0, s] * w[f, s] + bias[f, s]
// B=128, F=256, S=4096. HBM-write-bound: 512 MiB out.
//
// R16: R14's exact structure (FT=2, BT=8, x in 32 KB smem, zero in-loop
// global loads, filter-inner 16 KB-stride __stcs bursts) at 7 CTAs/SM
// (224 KB smem/SM, occ ~79%). Deconfounded occupancy step: R15 changed
// BT too; this changes ONLY CTAs/SM vs R14.

#define S4     1024        // float4 per row (4096 floats)
#define NFILT  256
#define BATCH  128
#define FT     2           // filters per block (w/bias register-cached)
#define BT     8           // batches per block (x staged in smem)
#define CHUNK4 256         // float4 per s-chunk, one per thread

__global__ __launch_bounds__(256, 7) void dense_filter_expand_kernel(
    const float4* __restrict__ x,     // [B, S4]
    const float4* __restrict__ w,     // [F, S4]
    const float4* __restrict__ bias,  // [F, S4]
    float4* __restrict__ out)         // [B, F, S4]
{
    __shared__ float4 xs[BT * CHUNK4];         // 32 KB

    const int t  = threadIdx.x;                // 0..255
    const int sc = blockIdx.x;                 // 0..3    s-chunk
    const int fg = blockIdx.y;                 // 0..127  filter group
    const int bg = blockIdx.z;                 // 0..15   batch group
    const int s4 = sc * CHUNK4 + t;            // float4 index within a row
    const int b0 = bg * BT;
    const int f0 = fg * FT;

    // Preamble: stage x chunks for 8 batches into smem (independent LDGs).
#pragma unroll
    for (int i = 0; i < BT; i++)
        xs[i * CHUNK4 + t] = __ldg(&x[(size_t)(b0 + i) * S4 + s4]);

    // Register-cache w/bias chunks for the 2 filters (16 regs).
    float4 wv[FT], bv[FT];
#pragma unroll
    for (int ff = 0; ff < FT; ff++) {
        wv[ff] = __ldg(&w[(size_t)(f0 + ff) * S4 + s4]);
        bv[ff] = __ldg(&bias[(size_t)(f0 + ff) * S4 + s4]);
    }
    __syncthreads();

    // Steady state: 1 LDS + 2 streaming stores per batch. Zero global loads.
#pragma unroll 1
    for (int bb = 0; bb < BT; bb++) {
        const float4 xv = xs[bb * CHUNK4 + t];

        float4* obase = out + ((size_t)(b0 + bb) * NFILT + f0) * S4 + s4;
#pragma unroll
        for (int ff = 0; ff < FT; ff++) {
            float4 o;
            o.x = fmaf(xv.x, wv[ff].x, bv[ff].x);
            o.y = fmaf(xv.y, wv[ff].y, bv[ff].y);
            o.z = fmaf(xv.z, wv[ff].z, bv[ff].z);
            o.w = fmaf(xv.w, wv[ff].w, bv[ff].w);
            // Streaming store: output is write-once, never re-read.
            __stcs(obase + (size_t)ff * S4, o);
        }
    }
}

extern "C" void kernel_launch(void* const* d_in, const int* in_sizes, int n_in,
                              void* d_out, int out_size) {
    const float4* x    = (const float4*)d_in[0];   // inputs [128,1,4096]
    const float4* w    = (const float4*)d_in[1];   // w [256,4096]
    const float4* bias = (const float4*)d_in[2];   // b [256,4096]
    float4* out = (float4*)d_out;

    dim3 grid(S4 / CHUNK4, NFILT / FT, BATCH / BT);  // (4, 128, 16) = 8192
    dense_filter_expand_kernel<<<grid, 256>>>(x, w, bias, out);
}